// round 4
// baseline (speedup 1.0000x reference)
#include <cuda_runtime.h>
#include <math.h>

// ---------------------------------------------------------------------------
// Problem constants
// ---------------------------------------------------------------------------
#define NN     1024
#define FF     128
#define MM     256
#define EE     8
#define W1COLS 260           // 2F+4
#define P_TOT  523776        // N*(N-1)/2
#define TILE   32            // i/j tile per block
#define NTILE  32            // N / TILE
#define MPAD   260           // padded smem row stride (260 % 32 == 4 -> conflict-free-ish)

typedef unsigned long long ull;

// ---------------------------------------------------------------------------
// Device scratch (no allocations allowed)
// ---------------------------------------------------------------------------
__device__ __align__(16) float g_pa[NN * MM];    // x @ W1a^T + cterm
__device__ __align__(16) float g_pb[NN * MM];    // x @ W1b^T
__device__ __align__(16) float g_W2f[EE * MM];   // W2 * bn_scale
__device__ float  g_cterm[MM];
__device__ float  g_b2f[EE];
__device__ float  g_w3[EE];
__device__ float  g_b3v;
__device__ double g_std[NN];
__device__ int    g_stressed[NN];

// ---------------------------------------------------------------------------
// f32x2 packed helpers (FFMA2 path — only reachable via PTX)
// ---------------------------------------------------------------------------
__device__ __forceinline__ ull add2(ull a, ull b) {
    ull r;
    asm("add.rn.f32x2 %0, %1, %2;" : "=l"(r) : "l"(a), "l"(b));
    return r;
}
__device__ __forceinline__ ull fma2(ull a, ull b, ull c) {
    ull r;
    asm("fma.rn.f32x2 %0, %1, %2, %3;" : "=l"(r) : "l"(a), "l"(b), "l"(c));
    return r;
}
__device__ __forceinline__ ull relu2(ull v) {
    float lo = __uint_as_float((unsigned)v);
    float hi = __uint_as_float((unsigned)(v >> 32));
    lo = fmaxf(lo, 0.0f);
    hi = fmaxf(hi, 0.0f);
    return (ull)__float_as_uint(lo) | ((ull)__float_as_uint(hi) << 32);
}

struct __align__(16) F4 { ull lo, hi; };
union U64 { ull u; float2 f; };

// ---------------------------------------------------------------------------
// Stress statistics: per-node std (ddof=1), done in fp64 (flips are disastrous)
// ---------------------------------------------------------------------------
__global__ void stress_std_kernel(const float* __restrict__ x) {
    int i = blockIdx.x;
    int t = threadIdx.x;
    double v  = (double)x[i * FF + t];
    double s  = v;
    double s2 = v * v;
    #pragma unroll
    for (int o = 16; o; o >>= 1) {
        s  += __shfl_down_sync(0xffffffffu, s,  o);
        s2 += __shfl_down_sync(0xffffffffu, s2, o);
    }
    __shared__ double ss[4], ss2[4];
    if ((t & 31) == 0) { ss[t >> 5] = s; ss2[t >> 5] = s2; }
    __syncthreads();
    if (t == 0) {
        double S  = ss[0] + ss[1] + ss[2] + ss[3];
        double S2 = ss2[0] + ss2[1] + ss2[2] + ss2[3];
        double var = (S2 - S * S / (double)FF) / (double)(FF - 1);
        g_std[i] = sqrt(var > 0.0 ? var : 0.0);
    }
}

__global__ void stress_flag_kernel() {
    int t = threadIdx.x;          // 1024 threads
    double v = g_std[t];
    double s = v;
    #pragma unroll
    for (int o = 16; o; o >>= 1) s += __shfl_down_sync(0xffffffffu, s, o);
    __shared__ double ws[32];
    if ((t & 31) == 0) ws[t >> 5] = s;
    __syncthreads();
    if (t < 32) {
        double u = ws[t];
        #pragma unroll
        for (int o = 16; o; o >>= 1) u += __shfl_down_sync(0xffffffffu, u, o);
        if (t == 0) ws[0] = u / (double)NN;
    }
    __syncthreads();
    g_stressed[t] = (v > ws[0]) ? 1 : 0;
}

// ---------------------------------------------------------------------------
// Prep: cterm, BN-fold into W2f/b2f, stash W3/b3
// ---------------------------------------------------------------------------
__global__ void prep_kernel(const float* __restrict__ ctx,
                            const float* __restrict__ W1,
                            const float* __restrict__ b1,
                            const float* __restrict__ gamma,
                            const float* __restrict__ beta,
                            const float* __restrict__ rmean,
                            const float* __restrict__ rvar,
                            const float* __restrict__ W2,
                            const float* __restrict__ b2,
                            const float* __restrict__ W3,
                            const float* __restrict__ b3) {
    int m = threadIdx.x;          // 256 threads
    __shared__ float sbias[MM];

    float ct = b1[m];
    #pragma unroll
    for (int k = 0; k < 4; k++) ct += ctx[k] * W1[m * W1COLS + 2 * FF + k];
    g_cterm[m] = ct;

    float sc = (float)((double)gamma[m] / sqrt((double)rvar[m] + 1e-5));
    float bias = beta[m] - rmean[m] * sc;
    sbias[m] = bias;
    #pragma unroll
    for (int e = 0; e < EE; e++) g_W2f[e * MM + m] = W2[e * MM + m] * sc;
    __syncthreads();

    int w = m >> 5, l = m & 31;
    if (w < EE) {
        float p = 0.0f;
        for (int mm = l; mm < MM; mm += 32) p += sbias[mm] * W2[w * MM + mm];
        #pragma unroll
        for (int o = 16; o; o >>= 1) p += __shfl_down_sync(0xffffffffu, p, o);
        if (l == 0) g_b2f[w] = b2[w] + p;
    }
    if (m < EE) g_w3[m] = W3[m];
    if (m == 0) g_b3v = b3[0];
}

// ---------------------------------------------------------------------------
// GEMM: g_pa[i,m] = x[i,:]@W1[m,0:128] + cterm[m];  g_pb[i,m] = x[i,:]@W1[m,128:256]
// Tile 64x64, 256 threads, each 4x4. K chunked 2x64.
// ---------------------------------------------------------------------------
__global__ __launch_bounds__(256) void gemm_kernel(const float* __restrict__ x,
                                                   const float* __restrict__ W1) {
    __shared__ float xs[64][68];
    __shared__ float ws[64][68];   // transposed: ws[k][c_local]
    int tid = threadIdx.x;
    int i0 = blockIdx.x * 64;
    int c0 = blockIdx.y * 64;      // c in [0,512): <256 -> pa, else pb
    int ti = tid >> 4, tj = tid & 15;

    float acc[4][4];
    #pragma unroll
    for (int r = 0; r < 4; r++)
        #pragma unroll
        for (int s = 0; s < 4; s++) acc[r][s] = 0.0f;

    for (int kb = 0; kb < FF; kb += 64) {
        // xs: coalesced
        for (int u = tid; u < 64 * 16; u += 256) {
            int r = u >> 4, q = u & 15;
            *(float4*)&xs[r][q * 4] =
                *(const float4*)&x[(i0 + r) * FF + kb + q * 4];
        }
        // ws transposed
        for (int u = tid; u < 64 * 16; u += 256) {
            int r = u & 63, q = u >> 6;   // r = local c, q = k group 0..15
            int c = c0 + r;
            int row = (c < MM) ? c : (c - MM);
            int off = (c < MM) ? 0 : FF;
            float4 v = *(const float4*)&W1[row * W1COLS + off + kb + q * 4];
            ws[q * 4 + 0][r] = v.x;
            ws[q * 4 + 1][r] = v.y;
            ws[q * 4 + 2][r] = v.z;
            ws[q * 4 + 3][r] = v.w;
        }
        __syncthreads();
        #pragma unroll 8
        for (int k = 0; k < 64; k++) {
            float a[4];
            #pragma unroll
            for (int r = 0; r < 4; r++) a[r] = xs[ti * 4 + r][k];
            float4 bv = *(const float4*)&ws[k][tj * 4];
            float b[4] = {bv.x, bv.y, bv.z, bv.w};
            #pragma unroll
            for (int r = 0; r < 4; r++)
                #pragma unroll
                for (int s = 0; s < 4; s++) acc[r][s] = fmaf(a[r], b[s], acc[r][s]);
        }
        __syncthreads();
    }
    #pragma unroll
    for (int r = 0; r < 4; r++) {
        int i = i0 + ti * 4 + r;
        #pragma unroll
        for (int s = 0; s < 4; s++) {
            int c = c0 + tj * 4 + s;
            if (c < MM) g_pa[i * MM + c] = acc[r][s] + g_cterm[c];
            else        g_pb[i * MM + (c - MM)] = acc[r][s];
        }
    }
}

// ---------------------------------------------------------------------------
// Pair kernel: the hot loop. Block = 32i x 32j tile, 256 threads, 2x2 pairs
// per thread, f32x2 FMA2 inner loop over M.
// ---------------------------------------------------------------------------
#define SMEM_PAIR ((64 * MPAD + EE * MPAD) * 4)

__global__ __launch_bounds__(256, 2) void pair_kernel(float* __restrict__ out,
                                                      int has_mask) {
    extern __shared__ float sm[];
    float* sa = sm;                       // 32 x MPAD
    float* sb = sm + TILE * MPAD;         // 32 x MPAD
    float* wf = sm + 2 * TILE * MPAD;     // 8 x MPAD

    // decode (bi, bj), bi <= bj
    int t = blockIdx.x, bi = 0;
    while (t >= NTILE - bi) { t -= NTILE - bi; bi++; }
    int bj = bi + t;
    int i0 = bi * TILE, j0 = bj * TILE;
    int tid = threadIdx.x;

    // cooperative loads (float4)
    for (int u = tid; u < TILE * (MM / 4); u += 256) {
        int r = u >> 6, q = u & 63;
        *(float4*)(sa + r * MPAD + q * 4) = *(const float4*)(g_pa + (i0 + r) * MM + q * 4);
        *(float4*)(sb + r * MPAD + q * 4) = *(const float4*)(g_pb + (j0 + r) * MM + q * 4);
    }
    for (int u = tid; u < EE * (MM / 4); u += 256) {
        int r = u >> 6, q = u & 63;
        *(float4*)(wf + r * MPAD + q * 4) = *(const float4*)(g_W2f + r * MM + q * 4);
    }
    __syncthreads();

    int ti2 = tid >> 4, tj2 = tid & 15;
    const float* pA = sa + (2 * ti2) * MPAD;
    const float* pB = sa + (2 * ti2 + 1) * MPAD;
    const float* qA = sb + (2 * tj2) * MPAD;
    const float* qB = sb + (2 * tj2 + 1) * MPAD;

    ull acc[4][EE];
    #pragma unroll
    for (int p = 0; p < 4; p++)
        #pragma unroll
        for (int e = 0; e < EE; e++) acc[p][e] = 0ull;

    #pragma unroll 2
    for (int m = 0; m < MM; m += 4) {
        F4 a0 = *(const F4*)(pA + m);
        F4 a1 = *(const F4*)(pB + m);
        F4 b0 = *(const F4*)(qA + m);
        F4 b1 = *(const F4*)(qB + m);

        ull r0 = relu2(add2(a0.lo, b0.lo));
        ull r1 = relu2(add2(a0.lo, b1.lo));
        ull r2 = relu2(add2(a1.lo, b0.lo));
        ull r3 = relu2(add2(a1.lo, b1.lo));
        const float* wp = wf + m;
        #pragma unroll
        for (int e = 0; e < EE; e++) {
            ull w = *(const ull*)(wp + e * MPAD);
            acc[0][e] = fma2(r0, w, acc[0][e]);
            acc[1][e] = fma2(r1, w, acc[1][e]);
            acc[2][e] = fma2(r2, w, acc[2][e]);
            acc[3][e] = fma2(r3, w, acc[3][e]);
        }
        r0 = relu2(add2(a0.hi, b0.hi));
        r1 = relu2(add2(a0.hi, b1.hi));
        r2 = relu2(add2(a1.hi, b0.hi));
        r3 = relu2(add2(a1.hi, b1.hi));
        #pragma unroll
        for (int e = 0; e < EE; e++) {
            ull w = *(const ull*)(wp + e * MPAD + 2);
            acc[0][e] = fma2(r0, w, acc[0][e]);
            acc[1][e] = fma2(r1, w, acc[1][e]);
            acc[2][e] = fma2(r2, w, acc[2][e]);
            acc[3][e] = fma2(r3, w, acc[3][e]);
        }
    }

    // epilogue
    float vb2[EE], vw3[EE];
    #pragma unroll
    for (int e = 0; e < EE; e++) { vb2[e] = g_b2f[e]; vw3[e] = g_w3[e]; }
    float bb3 = g_b3v;
    int iBase = i0 + 2 * ti2, jBase = j0 + 2 * tj2;

    #pragma unroll
    for (int pi = 0; pi < 2; pi++) {
        #pragma unroll
        for (int pj = 0; pj < 2; pj++) {
            int i = iBase + pi, j = jBase + pj;
            if (j <= i) continue;
            float z = bb3;
            #pragma unroll
            for (int e = 0; e < EE; e++) {
                U64 u; u.u = acc[pi * 2 + pj][e];
                float h = u.f.x + u.f.y + vb2[e];
                h = fmaxf(h, 0.0f);
                z = fmaf(h, vw3[e], z);
            }
            float s = 1.0f / (1.0f + expf(-z));
            unsigned p = (unsigned)(i * (2 * NN - i - 1) / 2 + (j - i - 1));
            out[p] = s;
            if (has_mask) {
                bool msk = (s > 0.5f) && g_stressed[i] && g_stressed[j];
                out[P_TOT + p] = msk ? 1.0f : 0.0f;
            }
        }
    }
}

// ---------------------------------------------------------------------------
// Launch
// ---------------------------------------------------------------------------
extern "C" void kernel_launch(void* const* d_in, const int* in_sizes, int n_in,
                              void* d_out, int out_size) {
    const float* x     = (const float*)d_in[0];
    const float* ctx   = (const float*)d_in[1];
    const float* W1    = (const float*)d_in[2];
    const float* b1    = (const float*)d_in[3];
    const float* gamma = (const float*)d_in[4];
    const float* beta  = (const float*)d_in[5];
    const float* rmean = (const float*)d_in[6];
    const float* rvar  = (const float*)d_in[7];
    const float* W2    = (const float*)d_in[8];
    const float* b2    = (const float*)d_in[9];
    const float* W3    = (const float*)d_in[10];
    const float* b3    = (const float*)d_in[11];
    float* out = (float*)d_out;

    (void)in_sizes; (void)n_in;

    stress_std_kernel<<<NN, FF>>>(x);
    stress_flag_kernel<<<1, NN>>>();
    prep_kernel<<<1, MM>>>(ctx, W1, b1, gamma, beta, rmean, rvar, W2, b2, W3, b3);
    gemm_kernel<<<dim3(NN / 64, 512 / 64), 256>>>(x, W1);

    cudaFuncSetAttribute(pair_kernel,
                         cudaFuncAttributeMaxDynamicSharedMemorySize, SMEM_PAIR);
    int has_mask = (out_size >= 2 * P_TOT) ? 1 : 0;
    int nblocks = NTILE * (NTILE + 1) / 2;   // 528
    pair_kernel<<<nblocks, 256, SMEM_PAIR>>>(out, has_mask);
}